// round 16
// baseline (speedup 1.0000x reference)
#include <cuda_runtime.h>
#include <cuda_bf16.h>
#include <cstdint>

// Problem constants
#define DIMC    192
#define QKV_N   576
#define NWIN    144
#define NHEADS  6
#define HD      32
#define TOW     64
#define BATCH   30
#define MTOT    (BATCH * TOW * NWIN)   // 276480 rows
#define TABLE   3312
#define ATT_SCALE 0.17677669529663687f
#define LOG2E     1.4426950408889634f

// Scratch
static __device__ float g_qkv[(size_t)MTOT * QKV_N];   // tf32-rounded; q scaled by ATT_SCALE*LOG2E
static __device__ float g_att[(size_t)MTOT * DIMC];    // tf32-rounded
static __device__ float g_xt[(size_t)MTOT * DIMC];     // tf32-rounded x
static __device__ float g_wq[(size_t)QKV_N * DIMC];    // tf32-rounded qkv_w
static __device__ float g_wp[(size_t)DIMC * DIMC];     // tf32-rounded proj_w
static __device__ float g_tableT[(size_t)TOW * NHEADS * TABLE]; // transposed, xLOG2E
static __device__ float g_biasg[(size_t)NHEADS * TOW * NWIN * NWIN]; // fragment-permuted, xLOG2E

// ---------------------------------------------------------------------------
// helpers
// ---------------------------------------------------------------------------
__device__ __forceinline__ uint32_t f32_to_tf32(float x) {
    uint32_t r;
    asm("cvt.rna.tf32.f32 %0, %1;" : "=r"(r) : "f"(x));
    return r;
}
__device__ __forceinline__ float ex2_approx(float x) {
    float r;
    asm("ex2.approx.f32 %0, %1;" : "=f"(r) : "f"(x));
    return r;
}
// pack two f32 into half2: lo -> low half, hi -> high half
__device__ __forceinline__ uint32_t h2pack(float lo, float hi) {
    uint32_t r;
    asm("cvt.rn.f16x2.f32 %0, %1, %2;" : "=r"(r) : "f"(hi), "f"(lo));
    return r;
}
__device__ __forceinline__ uint32_t smem_u32(const void* p) {
    uint32_t a;
    asm("{ .reg .u64 t; cvta.to.shared.u64 t, %1; cvt.u32.u64 %0, t; }"
        : "=r"(a) : "l"(p));
    return a;
}
__device__ __forceinline__ void cp16(uint32_t saddr, const void* g) {
    asm volatile("cp.async.cg.shared.global [%0], [%1], 16;"
                 :: "r"(saddr), "l"(g));
}
#define CP_COMMIT() asm volatile("cp.async.commit_group;" ::: "memory")
#define CP_WAIT(n)  asm volatile("cp.async.wait_group %0;" :: "n"(n) : "memory")

__device__ __forceinline__ void mma_tf32_16x8x8(
    float& c0, float& c1, float& c2, float& c3,
    uint32_t a0, uint32_t a1, uint32_t a2, uint32_t a3,
    uint32_t b0, uint32_t b1)
{
    asm volatile(
        "mma.sync.aligned.m16n8k8.row.col.f32.tf32.tf32.f32 "
        "{%0,%1,%2,%3}, {%4,%5,%6,%7}, {%8,%9}, {%0,%1,%2,%3};"
        : "+f"(c0), "+f"(c1), "+f"(c2), "+f"(c3)
        : "r"(a0), "r"(a1), "r"(a2), "r"(a3), "r"(b0), "r"(b1));
}

__device__ __forceinline__ void mma_f16_16x8x16(
    float& c0, float& c1, float& c2, float& c3,
    uint32_t a0, uint32_t a1, uint32_t a2, uint32_t a3,
    uint32_t b0, uint32_t b1)
{
    asm volatile(
        "mma.sync.aligned.m16n8k16.row.col.f32.f16.f16.f32 "
        "{%0,%1,%2,%3}, {%4,%5,%6,%7}, {%8,%9}, {%0,%1,%2,%3};"
        : "+f"(c0), "+f"(c1), "+f"(c2), "+f"(c3)
        : "r"(a0), "r"(a1), "r"(a2), "r"(a3), "r"(b0), "r"(b1));
}

// ---------------------------------------------------------------------------
// Elementwise tf32 pre-round
// ---------------------------------------------------------------------------
__global__ void cvt_tf32_kernel(const float* __restrict__ in,
                                float* __restrict__ out, int n4)
{
    int i = blockIdx.x * blockDim.x + threadIdx.x;
    if (i < n4) {
        float4 v = ((const float4*)in)[i];
        v.x = __uint_as_float(f32_to_tf32(v.x));
        v.y = __uint_as_float(f32_to_tf32(v.y));
        v.z = __uint_as_float(f32_to_tf32(v.z));
        v.w = __uint_as_float(f32_to_tf32(v.w));
        ((float4*)out)[i] = v;
    }
}

// ---------------------------------------------------------------------------
// tf32 GEMM, 3-stage cp.async pipeline (unchanged).
// ---------------------------------------------------------------------------
#define GKK 192
#define KITERS 6
#define APITCH 36
#define AS_WORDS (128 * APITCH)
#define BS_WORDS (64 * APITCH)
#define STAGE_WORDS (AS_WORDS + BS_WORDS)          // 6912
#define GEMM_SMEM_B (3 * STAGE_WORDS * 4)          // 82944

__global__ __launch_bounds__(256)
void gemm_tc_kernel(const float* __restrict__ A, const float* __restrict__ B,
                    const float* __restrict__ bias, float* __restrict__ C,
                    int N, int scaleCols, float scale, int roundOut)
{
    extern __shared__ uint32_t gsm[];

    const int tid  = threadIdx.x;
    const int warp = tid >> 5, lane = tid & 31;
    const int wm   = warp & 3, wn = warp >> 2;
    const int grp  = lane >> 2, tg = lane & 3;
    const int n0   = blockIdx.x * 64;
    const int m0   = blockIdx.y * 128;

    const float* Ag = A + (size_t)m0 * GKK;
    const float* Bg = B + (size_t)n0 * GKK;
    const int crow = tid >> 3, ccol = (tid & 7) * 4;
    const uint32_t sbase = smem_u32(gsm);

    auto issue_copy = [&](int s, int ki) {
        const int k0 = ki * 32;
        uint32_t abase = sbase + (uint32_t)(s * STAGE_WORDS) * 4;
        uint32_t bbase = abase + AS_WORDS * 4;
#pragma unroll
        for (int it = 0; it < 4; it++)
            cp16(abase + ((crow + it * 32) * APITCH + ccol) * 4,
                 &Ag[(size_t)(crow + it * 32) * GKK + k0 + ccol]);
#pragma unroll
        for (int it = 0; it < 2; it++)
            cp16(bbase + ((crow + it * 32) * APITCH + ccol) * 4,
                 &Bg[(size_t)(crow + it * 32) * GKK + k0 + ccol]);
        CP_COMMIT();
    };

    float c[2][4][4];
#pragma unroll
    for (int mt = 0; mt < 2; mt++)
#pragma unroll
        for (int nt = 0; nt < 4; nt++)
#pragma unroll
            for (int r = 0; r < 4; r++) c[mt][nt][r] = 0.f;

    issue_copy(0, 0);
    issue_copy(1, 1);

#pragma unroll
    for (int i = 0; i < KITERS; i++) {
        if (i < KITERS - 1) { CP_WAIT(1); } else { CP_WAIT(0); }
        __syncthreads();

        const uint32_t* As = gsm + (i % 3) * STAGE_WORDS;
        const uint32_t* Bs = As + AS_WORDS;
#pragma unroll
        for (int ks = 0; ks < 4; ks++) {
            const int k8 = ks * 8;
            uint32_t a[2][4];
#pragma unroll
            for (int mt = 0; mt < 2; mt++) {
                int rbw = wm * 32 + mt * 16;
                a[mt][0] = As[(rbw + grp) * APITCH + k8 + tg];
                a[mt][1] = As[(rbw + grp + 8) * APITCH + k8 + tg];
                a[mt][2] = As[(rbw + grp) * APITCH + k8 + tg + 4];
                a[mt][3] = As[(rbw + grp + 8) * APITCH + k8 + tg + 4];
            }
#pragma unroll
            for (int nt = 0; nt < 4; nt++) {
                int nb = wn * 32 + nt * 8;
                uint32_t b0 = Bs[(nb + grp) * APITCH + k8 + tg];
                uint32_t b1 = Bs[(nb + grp) * APITCH + k8 + tg + 4];
#pragma unroll
                for (int mt = 0; mt < 2; mt++)
                    mma_tf32_16x8x8(c[mt][nt][0], c[mt][nt][1],
                                    c[mt][nt][2], c[mt][nt][3],
                                    a[mt][0], a[mt][1], a[mt][2], a[mt][3],
                                    b0, b1);
            }
        }
        if (i + 2 < KITERS) issue_copy((i + 2) % 3, i + 2);
    }

#pragma unroll
    for (int mt = 0; mt < 2; mt++) {
#pragma unroll
        for (int nt = 0; nt < 4; nt++) {
            int col = n0 + wn * 32 + nt * 8 + tg * 2;
            float b0 = bias[col], b1 = bias[col + 1];
            float s0 = (col     < scaleCols) ? scale : 1.f;
            float s1 = (col + 1 < scaleCols) ? scale : 1.f;
            int r0 = m0 + wm * 32 + mt * 16 + grp;
            float v00 = (c[mt][nt][0] + b0) * s0;
            float v01 = (c[mt][nt][1] + b1) * s1;
            float v10 = (c[mt][nt][2] + b0) * s0;
            float v11 = (c[mt][nt][3] + b1) * s1;
            if (roundOut) {
                v00 = __uint_as_float(f32_to_tf32(v00));
                v01 = __uint_as_float(f32_to_tf32(v01));
                v10 = __uint_as_float(f32_to_tf32(v10));
                v11 = __uint_as_float(f32_to_tf32(v11));
            }
            *(float2*)&C[(size_t)r0 * N + col]       = make_float2(v00, v01);
            *(float2*)&C[(size_t)(r0 + 8) * N + col] = make_float2(v10, v11);
        }
    }
}

// ---------------------------------------------------------------------------
// Table transpose: table[p][w][h] -> g_tableT[w][h][p], scaled by LOG2E.
// ---------------------------------------------------------------------------
__global__ void table_transpose_kernel(const float* __restrict__ table)
{
    const int w = blockIdx.x, h = blockIdx.y;
    float* dst = g_tableT + (size_t)(w * NHEADS + h) * TABLE;
    for (int p = threadIdx.x; p < TABLE; p += blockDim.x)
        dst[p] = table[((size_t)p * TOW + w) * NHEADS + h] * LOG2E;
}

// ---------------------------------------------------------------------------
// Bias pre-gather into FRAGMENT-PERMUTED layout (reads L1-resident slice).
// ---------------------------------------------------------------------------
__global__ void bias_gather_kernel(const int* __restrict__ pos)
{
    const int w = blockIdx.x, h = blockIdx.y;
    const float* src = g_tableT + (size_t)(w * NHEADS + h) * TABLE;
    float* dst = g_biasg + (size_t)(h * TOW + w) * (NWIN * NWIN);
    for (int op = threadIdx.x; op < NWIN * NWIN; op += blockDim.x) {
        const int sw   = op / 2304;          // seg*3+warp
        const int rem  = op % 2304;
        const int nt   = rem / 128;
        const int rem2 = rem % 128;
        const int half = rem2 / 64;
        const int l2   = rem2 % 64;
        const int lane = l2 / 2, bb = l2 % 2;
        const int grp  = lane / 4, tg = lane % 4;
        const int i = (sw / 3) * 48 + (sw % 3) * 16 + half * 8 + grp;
        const int j = nt * 8 + tg * 2 + bb;
        dst[op] = src[pos[i * NWIN + j]];
    }
}

// ---------------------------------------------------------------------------
// Flash-style attention v11: register S; QK^T in tf32; PV in f16 m16n8k16
// (P C-frag == f16 A-frag => ZERO shuffles; f16 mantissa == tf32 mantissa).
// V staged as half2 token-pairs vh[i2][e], pitch 40 (bank-conflict-free).
// 96 thr, 3 warps, 48 rows/CTA. smem: KV union 23040B + Qs 6912B = 29952B.
// ---------------------------------------------------------------------------
#define ATTN_THREADS 96
#define SEG_ROWS 48
#define NSEG 3
#define KP  36
#define VHP 40
#define QP  36
#define KV_WORDS (NWIN * VHP)                 // 5760 (K tf32 fits: 144*36=5184)
#define QS_OFF   KV_WORDS
#define ATTN_SMEM_B ((KV_WORDS + SEG_ROWS * QP) * 4)   // 29952

__global__ __launch_bounds__(ATTN_THREADS)
void attn_mma_kernel()
{
    extern __shared__ uint32_t smw[];
    uint32_t* KV = smw;          // K (tf32, pitch 36) then vh (half2, pitch 40)
    uint32_t* Qs = smw + QS_OFF;

    const int w = blockIdx.x, b = blockIdx.y;
    const int h = blockIdx.z / NSEG, seg = blockIdx.z % NSEG;
    const int tid  = threadIdx.x;
    const int warp = tid >> 5, lane = tid & 31;
    const int grp  = lane >> 2, tg = lane & 3;
    const int lrb  = warp * 16;
    const int rb   = seg * SEG_ROWS + lrb;

    const size_t base = (size_t)(b * TOW + w) * NWIN * QKV_N + h * HD;
    const float* __restrict__ Qg = g_qkv + base;
    const float* __restrict__ Kg = Qg + 192;
    const float* __restrict__ Vg = Qg + 384;
    const uint32_t kvbase = smem_u32(KV);
    const uint32_t qsbase = smem_u32(Qs);

    // --- phase 1: cp.async K (pitch 36) + Q segment (pitch 36) ---
    for (int idx = tid; idx < NWIN * 8; idx += ATTN_THREADS) {
        const int i = idx >> 3, e0 = (idx & 7) * 4;
        cp16(kvbase + (i * KP + e0) * 4, &Kg[(size_t)i * QKV_N + e0]);
    }
    for (int idx = tid; idx < SEG_ROWS * 8; idx += ATTN_THREADS) {
        const int i = idx >> 3, e0 = (idx & 7) * 4;
        cp16(qsbase + (i * QP + e0) * 4,
             &Qg[(size_t)(seg * SEG_ROWS + i) * QKV_N + e0]);
    }
    CP_COMMIT();
    CP_WAIT(0);
    __syncthreads();

    // Q fragments from smem
    uint32_t aq[4][4];
#pragma unroll
    for (int kt = 0; kt < 4; kt++) {
        const int k8 = kt * 8;
        aq[kt][0] = Qs[(lrb + grp) * QP + k8 + tg];
        aq[kt][1] = Qs[(lrb + grp + 8) * QP + k8 + tg];
        aq[kt][2] = Qs[(lrb + grp) * QP + k8 + tg + 4];
        aq[kt][3] = Qs[(lrb + grp + 8) * QP + k8 + tg + 4];
    }

    // --- phase 2: S = Q K^T + bias (registers) ---
    const float* bptr = g_biasg + (size_t)(h * TOW + w) * (NWIN * NWIN)
                        + (size_t)(seg * 3 + warp) * 2304;
    float sc[18][4];
#pragma unroll 3
    for (int nt = 0; nt < 18; nt++) {
        const int nb = nt * 8;
        float c0 = 0.f, c1 = 0.f, c2 = 0.f, c3 = 0.f;
        float d0 = 0.f, d1 = 0.f, d2 = 0.f, d3 = 0.f;
#pragma unroll
        for (int kt = 0; kt < 2; kt++) {
            const int k8 = kt * 8;
            uint32_t b0 = KV[(nb + grp) * KP + k8 + tg];
            uint32_t b1 = KV[(nb + grp) * KP + k8 + tg + 4];
            mma_tf32_16x8x8(c0, c1, c2, c3,
                            aq[kt][0], aq[kt][1], aq[kt][2], aq[kt][3], b0, b1);
        }
#pragma unroll
        for (int kt = 2; kt < 4; kt++) {
            const int k8 = kt * 8;
            uint32_t b0 = KV[(nb + grp) * KP + k8 + tg];
            uint32_t b1 = KV[(nb + grp) * KP + k8 + tg + 4];
            mma_tf32_16x8x8(d0, d1, d2, d3,
                            aq[kt][0], aq[kt][1], aq[kt][2], aq[kt][3], b0, b1);
        }
        float2 bv0 = *(const float2*)&bptr[nt * 128 + lane * 2];
        float2 bv1 = *(const float2*)&bptr[nt * 128 + 64 + lane * 2];
        sc[nt][0] = (c0 + d0) + bv0.x; sc[nt][1] = (c1 + d1) + bv0.y;
        sc[nt][2] = (c2 + d2) + bv1.x; sc[nt][3] = (c3 + d3) + bv1.y;
    }
    __syncthreads();   // K consumed; KV buffer free for vh

    // --- phase 3: stage V as half2 token-pairs (overlaps softmax) ---
    // vh[i2][e] = half2(V[2*i2][e], V[2*i2+1][e]), pitch VHP=40
    for (int idx = tid; idx < 72 * 8; idx += ATTN_THREADS) {
        const int i2 = idx >> 3, e0 = (idx & 7) * 4;
        const float* v0 = &Vg[(size_t)(2 * i2) * QKV_N + e0];
        float4 r0 = *(const float4*)v0;
        float4 r1 = *(const float4*)(v0 + QKV_N);
        uint4 hq;
        hq.x = h2pack(r0.x, r1.x);
        hq.y = h2pack(r0.y, r1.y);
        hq.z = h2pack(r0.z, r1.z);
        hq.w = h2pack(r0.w, r1.w);
        *(uint4*)&KV[i2 * VHP + e0] = hq;
    }

    float inv0, inv1;
    uint32_t ph[36];   // packed P: ph[2nt]=rows grp (cols 2tg,2tg+1), ph[2nt+1]=rows grp+8
    {
        float mx0 = -1e30f, mx1 = -1e30f;
#pragma unroll
        for (int nt = 0; nt < 18; nt++) {
            mx0 = fmaxf(mx0, fmaxf(sc[nt][0], sc[nt][1]));
            mx1 = fmaxf(mx1, fmaxf(sc[nt][2], sc[nt][3]));
        }
        mx0 = fmaxf(mx0, __shfl_xor_sync(0xffffffffu, mx0, 1));
        mx0 = fmaxf(mx0, __shfl_xor_sync(0xffffffffu, mx0, 2));
        mx1 = fmaxf(mx1, __shfl_xor_sync(0xffffffffu, mx1, 1));
        mx1 = fmaxf(mx1, __shfl_xor_sync(0xffffffffu, mx1, 2));
        float s0 = 0.f, s1 = 0.f;
#pragma unroll
        for (int nt = 0; nt < 18; nt++) {
            sc[nt][0] = ex2_approx(sc[nt][0] - mx0); s0 += sc[nt][0];
            sc[nt][1] = ex2_approx(sc[nt][1] - mx0); s0 += sc[nt][1];
            sc[nt][2] = ex2_approx(sc[nt][2] - mx1); s1 += sc[nt][2];
            sc[nt][3] = ex2_approx(sc[nt][3] - mx1); s1 += sc[nt][3];
        }
        s0 += __shfl_xor_sync(0xffffffffu, s0, 1);
        s0 += __shfl_xor_sync(0xffffffffu, s0, 2);
        s1 += __shfl_xor_sync(0xffffffffu, s1, 1);
        s1 += __shfl_xor_sync(0xffffffffu, s1, 2);
        inv0 = 1.f / s0; inv1 = 1.f / s1;
        // pack unnormalized P to f16 pairs (exactly the f16 A-fragment layout)
#pragma unroll
        for (int nt = 0; nt < 18; nt++) {
            ph[2 * nt]     = h2pack(sc[nt][0], sc[nt][1]);
            ph[2 * nt + 1] = h2pack(sc[nt][2], sc[nt][3]);
        }
    }
    __syncthreads();   // vh staged

    // --- phase 4: O = P V in f16 m16n8k16 (9 k-steps, no shuffles) ---
    float c[4][4];
#pragma unroll
    for (int nt = 0; nt < 4; nt++)
#pragma unroll
        for (int r = 0; r < 4; r++) c[nt][r] = 0.f;

#pragma unroll
    for (int kk = 0; kk < 9; kk++) {
        const uint32_t a0 = ph[4 * kk + 0];   // P[grp][16kk+2tg..]
        const uint32_t a1 = ph[4 * kk + 1];   // P[grp+8][..]
        const uint32_t a2 = ph[4 * kk + 2];   // P[grp][16kk+8+2tg..]
        const uint32_t a3 = ph[4 * kk + 3];   // P[grp+8][..]
        const int r0 = (8 * kk + tg) * VHP;
        const int r1 = (8 * kk + tg + 4) * VHP;
#pragma unroll
        for (int nt = 0; nt < 4; nt++) {
            const int e = nt * 8 + grp;
            uint32_t b0 = KV[r0 + e];   // tokens 16kk+2tg, +1
            uint32_t b1 = KV[r1 + e];   // tokens 16kk+8+2tg, +1
            mma_f16_16x8x16(c[nt][0], c[nt][1], c[nt][2], c[nt][3],
                            a0, a1, a2, a3, b0, b1);
        }
    }

    const size_t obase = (size_t)(b * TOW + w) * NWIN * DIMC + h * HD;
#pragma unroll
    for (int nt = 0; nt < 4; nt++) {
        const int col = nt * 8 + tg * 2;
        float o00 = __uint_as_float(f32_to_tf32(c[nt][0] * inv0));
        float o01 = __uint_as_float(f32_to_tf32(c[nt][1] * inv0));
        float o10 = __uint_as_float(f32_to_tf32(c[nt][2] * inv1));
        float o11 = __uint_as_float(f32_to_tf32(c[nt][3] * inv1));
        *(float2*)&g_att[obase + (size_t)(rb + grp) * DIMC + col] =
            make_float2(o00, o01);
        *(float2*)&g_att[obase + (size_t)(rb + grp + 8) * DIMC + col] =
            make_float2(o10, o11);
    }
}

// ---------------------------------------------------------------------------
extern "C" void kernel_launch(void* const* d_in, const int* in_sizes, int n_in,
                              void* d_out, int out_size)
{
    const float* x      = (const float*)d_in[0];
    const float* qkv_w  = (const float*)d_in[1];
    const float* qkv_b  = (const float*)d_in[2];
    const float* proj_w = (const float*)d_in[3];
    const float* proj_b = (const float*)d_in[4];
    const float* table  = (const float*)d_in[5];
    const int*   pos    = (const int*)d_in[6];
    float* out = (float*)d_out;

    float *qkv_s, *att_s, *xt_s, *wq_s, *wp_s;
    cudaGetSymbolAddress((void**)&qkv_s, g_qkv);
    cudaGetSymbolAddress((void**)&att_s, g_att);
    cudaGetSymbolAddress((void**)&xt_s,  g_xt);
    cudaGetSymbolAddress((void**)&wq_s,  g_wq);
    cudaGetSymbolAddress((void**)&wp_s,  g_wp);

    cudaFuncSetAttribute(gemm_tc_kernel, cudaFuncAttributeMaxDynamicSharedMemorySize,
                         GEMM_SMEM_B);
    cudaFuncSetAttribute(attn_mma_kernel, cudaFuncAttributeMaxDynamicSharedMemorySize,
                         ATTN_SMEM_B);

    // 0) pre-round inputs to tf32; transpose bias table (xLOG2E)
    {
        int n4 = MTOT * DIMC / 4;
        cvt_tf32_kernel<<<(n4 + 255) / 256, 256>>>(x, xt_s, n4);
        int w4 = QKV_N * DIMC / 4;
        cvt_tf32_kernel<<<(w4 + 255) / 256, 256>>>(qkv_w, wq_s, w4);
        int p4 = DIMC * DIMC / 4;
        cvt_tf32_kernel<<<(p4 + 255) / 256, 256>>>(proj_w, wp_s, p4);
        dim3 tg_(TOW, NHEADS);
        table_transpose_kernel<<<tg_, 256>>>(table);
    }
    // 1) bias pre-gather (fragment-permuted layout, L1-local source)
    {
        dim3 grid(TOW, NHEADS);
        bias_gather_kernel<<<grid, 256>>>(pos);
    }
    // 2) fused QKV projection (q scaled by ATT_SCALE*LOG2E for exp2 softmax)
    {
        dim3 grid(QKV_N / 64, MTOT / 128);
        gemm_tc_kernel<<<grid, 256, GEMM_SMEM_B>>>(xt_s, wq_s, qkv_b, qkv_s,
                                                   QKV_N, DIMC,
                                                   ATT_SCALE * LOG2E, 1);
    }
    // 3) windowed attention (tf32 QK^T + f16 PV)
    {
        dim3 grid(TOW, BATCH, NHEADS * NSEG);
        attn_mma_kernel<<<grid, ATTN_THREADS, ATTN_SMEM_B>>>();
    }
    // 4) output projection
    {
        dim3 grid(DIMC / 64, MTOT / 128);
        gemm_tc_kernel<<<grid, 256, GEMM_SMEM_B>>>(att_s, wp_s, proj_b, out,
                                                   DIMC, 0, 1.0f, 0);
    }
}

// round 17
// speedup vs baseline: 1.3254x; 1.3254x over previous
#include <cuda_runtime.h>
#include <cuda_fp16.h>
#include <cstdint>

// Problem constants
#define DIMC    192
#define QKV_N   576
#define NWIN    144
#define NHEADS  6
#define HD      32
#define TOW     64
#define BATCH   30
#define MTOT    (BATCH * TOW * NWIN)   // 276480 rows
#define TABLE   3312
#define ATT_SCALE 0.17677669529663687f
#define LOG2E     1.4426950408889634f

// Scratch (f16 data plane, stored as half2 words)
static __device__ uint32_t g_qkv[(size_t)MTOT * QKV_N / 2]; // half; q scaled by ATT_SCALE*LOG2E
static __device__ uint32_t g_att[(size_t)MTOT * DIMC / 2];  // half
static __device__ uint32_t g_xt[(size_t)MTOT * DIMC / 2];   // half x
static __device__ uint32_t g_wq[(size_t)QKV_N * DIMC / 2];  // half qkv_w
static __device__ uint32_t g_wp[(size_t)DIMC * DIMC / 2];   // half proj_w
static __device__ float g_tableT[(size_t)TOW * NHEADS * TABLE];           // xLOG2E
static __device__ float g_biasg[(size_t)NHEADS * TOW * NWIN * NWIN];      // fragment-permuted, xLOG2E

// ---------------------------------------------------------------------------
// helpers
// ---------------------------------------------------------------------------
__device__ __forceinline__ uint32_t f32_to_tf32(float x) {
    uint32_t r;
    asm("cvt.rna.tf32.f32 %0, %1;" : "=r"(r) : "f"(x));
    return r;
}
__device__ __forceinline__ float ex2_approx(float x) {
    float r;
    asm("ex2.approx.f32 %0, %1;" : "=f"(r) : "f"(x));
    return r;
}
// pack two f32 into half2 word: lo -> low half, hi -> high half
__device__ __forceinline__ uint32_t h2pack(float lo, float hi) {
    uint32_t r;
    asm("cvt.rn.f16x2.f32 %0, %1, %2;" : "=r"(r) : "f"(hi), "f"(lo));
    return r;
}
__device__ __forceinline__ uint32_t smem_u32(const void* p) {
    uint32_t a;
    asm("{ .reg .u64 t; cvta.to.shared.u64 t, %1; cvt.u32.u64 %0, t; }"
        : "=r"(a) : "l"(p));
    return a;
}
__device__ __forceinline__ void cp16(uint32_t saddr, const void* g) {
    asm volatile("cp.async.cg.shared.global [%0], [%1], 16;"
                 :: "r"(saddr), "l"(g));
}
#define CP_COMMIT() asm volatile("cp.async.commit_group;" ::: "memory")
#define CP_WAIT(n)  asm volatile("cp.async.wait_group %0;" :: "n"(n) : "memory")

__device__ __forceinline__ void mma_f16_16x8x16(
    float& c0, float& c1, float& c2, float& c3,
    uint32_t a0, uint32_t a1, uint32_t a2, uint32_t a3,
    uint32_t b0, uint32_t b1)
{
    asm volatile(
        "mma.sync.aligned.m16n8k16.row.col.f32.f16.f16.f32 "
        "{%0,%1,%2,%3}, {%4,%5,%6,%7}, {%8,%9}, {%0,%1,%2,%3};"
        : "+f"(c0), "+f"(c1), "+f"(c2), "+f"(c3)
        : "r"(a0), "r"(a1), "r"(a2), "r"(a3), "r"(b0), "r"(b1));
}

// ---------------------------------------------------------------------------
// Elementwise f32 -> f16 pre-round (float4 -> 4 halves)
// ---------------------------------------------------------------------------
__global__ void cvt_f16_kernel(const float* __restrict__ in,
                               uint32_t* __restrict__ out, int n4)
{
    int i = blockIdx.x * blockDim.x + threadIdx.x;
    if (i < n4) {
        float4 v = ((const float4*)in)[i];
        uint2 o;
        o.x = h2pack(v.x, v.y);
        o.y = h2pack(v.z, v.w);
        ((uint2*)out)[i] = o;
    }
}

// ---------------------------------------------------------------------------
// f16 GEMM, 3-stage cp.async pipeline.
// C[M,N] = A[M,192] @ B[N,192]^T + bias[N]; cols<scaleCols *= scale.
// A,B are half (k-contiguous). Output: half2 to Ch if halfOut else float to Cf.
// CTA 128x64, BK=32 halves, 256 thr (8 warps 4x2), warp tile 32x32, k16 mma.
// ---------------------------------------------------------------------------
#define GKK 192
#define KITERS 6
#define PW 20                               // words (half2) per 32-half row slab
#define AS_W (128 * PW)                     // 2560
#define BS_W (64 * PW)                      // 1280
#define STAGE_W (AS_W + BS_W)               // 3840
#define GEMM_SMEM_B (3 * STAGE_W * 4)       // 46080

__global__ __launch_bounds__(256)
void gemm_f16_kernel(const __half* __restrict__ A, const __half* __restrict__ B,
                     const float* __restrict__ bias,
                     float* __restrict__ Cf, uint32_t* __restrict__ Ch,
                     int N, int scaleCols, float scale, int halfOut)
{
    extern __shared__ uint32_t gsm[];

    const int tid  = threadIdx.x;
    const int warp = tid >> 5, lane = tid & 31;
    const int wm   = warp & 3, wn = warp >> 2;
    const int grp  = lane >> 2, tg = lane & 3;
    const int n0   = blockIdx.x * 64;
    const int m0   = blockIdx.y * 128;

    const __half* Ag = A + (size_t)m0 * GKK;
    const __half* Bg = B + (size_t)n0 * GKK;
    const uint32_t sbase = smem_u32(gsm);

    auto issue_copy = [&](int s, int ki) {
        const int k0 = ki * 32;             // halves
        uint32_t abase = sbase + (uint32_t)(s * STAGE_W) * 4;
        uint32_t bbase = abase + AS_W * 4;
#pragma unroll
        for (int it = 0; it < 2; it++) {
            int idx = tid + it * 256;       // 512 cp16 for A
            int row = idx >> 2, wc = idx & 3;
            cp16(abase + (uint32_t)(row * PW + wc * 4) * 4,
                 &Ag[(size_t)row * GKK + k0 + wc * 8]);
        }
        {
            int row = tid >> 2, wc = tid & 3;   // 256 cp16 for B
            cp16(bbase + (uint32_t)(row * PW + wc * 4) * 4,
                 &Bg[(size_t)row * GKK + k0 + wc * 8]);
        }
        CP_COMMIT();
    };

    float c[2][4][4];
#pragma unroll
    for (int mt = 0; mt < 2; mt++)
#pragma unroll
        for (int nt = 0; nt < 4; nt++)
#pragma unroll
            for (int r = 0; r < 4; r++) c[mt][nt][r] = 0.f;

    issue_copy(0, 0);
    issue_copy(1, 1);

#pragma unroll
    for (int i = 0; i < KITERS; i++) {
        if (i < KITERS - 1) { CP_WAIT(1); } else { CP_WAIT(0); }
        __syncthreads();

        const uint32_t* As = gsm + (i % 3) * STAGE_W;
        const uint32_t* Bs = As + AS_W;
#pragma unroll
        for (int kb = 0; kb < 2; kb++) {
            const int k8 = kb * 8;
            uint32_t a[2][4];
#pragma unroll
            for (int mt = 0; mt < 2; mt++) {
                int rbw = wm * 32 + mt * 16;
                a[mt][0] = As[(rbw + grp) * PW + k8 + tg];
                a[mt][1] = As[(rbw + grp + 8) * PW + k8 + tg];
                a[mt][2] = As[(rbw + grp) * PW + k8 + tg + 4];
                a[mt][3] = As[(rbw + grp + 8) * PW + k8 + tg + 4];
            }
#pragma unroll
            for (int nt = 0; nt < 4; nt++) {
                int nb = wn * 32 + nt * 8;
                uint32_t b0 = Bs[(nb + grp) * PW + k8 + tg];
                uint32_t b1 = Bs[(nb + grp) * PW + k8 + tg + 4];
#pragma unroll
                for (int mt = 0; mt < 2; mt++)
                    mma_f16_16x8x16(c[mt][nt][0], c[mt][nt][1],
                                    c[mt][nt][2], c[mt][nt][3],
                                    a[mt][0], a[mt][1], a[mt][2], a[mt][3],
                                    b0, b1);
            }
        }
        if (i + 2 < KITERS) issue_copy((i + 2) % 3, i + 2);
    }

#pragma unroll
    for (int mt = 0; mt < 2; mt++) {
#pragma unroll
        for (int nt = 0; nt < 4; nt++) {
            int col = n0 + wn * 32 + nt * 8 + tg * 2;
            float b0 = bias[col], b1 = bias[col + 1];
            float s0 = (col     < scaleCols) ? scale : 1.f;
            float s1 = (col + 1 < scaleCols) ? scale : 1.f;
            int r0 = m0 + wm * 32 + mt * 16 + grp;
            float v00 = (c[mt][nt][0] + b0) * s0;
            float v01 = (c[mt][nt][1] + b1) * s1;
            float v10 = (c[mt][nt][2] + b0) * s0;
            float v11 = (c[mt][nt][3] + b1) * s1;
            if (halfOut) {
                Ch[((size_t)r0 * N + col) >> 1]       = h2pack(v00, v01);
                Ch[((size_t)(r0 + 8) * N + col) >> 1] = h2pack(v10, v11);
            } else {
                *(float2*)&Cf[(size_t)r0 * N + col]       = make_float2(v00, v01);
                *(float2*)&Cf[(size_t)(r0 + 8) * N + col] = make_float2(v10, v11);
            }
        }
    }
}

// ---------------------------------------------------------------------------
// Table transpose: table[p][w][h] -> g_tableT[w][h][p], scaled by LOG2E.
// ---------------------------------------------------------------------------
__global__ void table_transpose_kernel(const float* __restrict__ table)
{
    const int w = blockIdx.x, h = blockIdx.y;
    float* dst = g_tableT + (size_t)(w * NHEADS + h) * TABLE;
    for (int p = threadIdx.x; p < TABLE; p += blockDim.x)
        dst[p] = table[((size_t)p * TOW + w) * NHEADS + h] * LOG2E;
}

// ---------------------------------------------------------------------------
// Bias pre-gather into FRAGMENT-PERMUTED layout (L1-resident source).
// ---------------------------------------------------------------------------
__global__ void bias_gather_kernel(const int* __restrict__ pos)
{
    const int w = blockIdx.x, h = blockIdx.y;
    const float* src = g_tableT + (size_t)(w * NHEADS + h) * TABLE;
    float* dst = g_biasg + (size_t)(h * TOW + w) * (NWIN * NWIN);
    for (int op = threadIdx.x; op < NWIN * NWIN; op += blockDim.x) {
        const int sw   = op / 2304;
        const int rem  = op % 2304;
        const int nt   = rem / 128;
        const int rem2 = rem % 128;
        const int half = rem2 / 64;
        const int l2   = rem2 % 64;
        const int lane = l2 / 2, bb = l2 % 2;
        const int grp  = lane / 4, tg = lane % 4;
        const int i = (sw / 3) * 48 + (sw % 3) * 16 + half * 8 + grp;
        const int j = nt * 8 + tg * 2 + bb;
        dst[op] = src[pos[i * NWIN + j]];
    }
}

// ---------------------------------------------------------------------------
// Flash-style attention v12: all-f16 operands, register S.
// QK^T: m16n8k16 f16 (K staged pitch-20 words); PV: m16n8k16 f16 (V as
// token-pair half2, pitch 40). 96 thr, 3 warps, 48 rows/CTA.
// smem: KV union 2880 words (11.5KB) + Qs 960 words = 15360 B.
// ---------------------------------------------------------------------------
#define ATTN_THREADS 96
#define SEG_ROWS 48
#define NSEG 3
#define KPW 20
#define VHP 40
#define QPW 20
#define KV_WORDS (NWIN * KPW)                 // 2880 (vh: 72*40 = 2880 too)
#define QS_OFF   KV_WORDS
#define ATTN_SMEM_B ((KV_WORDS + SEG_ROWS * QPW) * 4)   // 15360

__global__ __launch_bounds__(ATTN_THREADS)
void attn_mma_kernel()
{
    extern __shared__ uint32_t smw[];
    uint32_t* KV = smw;          // K (pitch 20) then vh (token-pair, pitch 40)
    uint32_t* Qs = smw + QS_OFF;

    const int w = blockIdx.x, b = blockIdx.y;
    const int h = blockIdx.z / NSEG, seg = blockIdx.z % NSEG;
    const int tid  = threadIdx.x;
    const int warp = tid >> 5, lane = tid & 31;
    const int grp  = lane >> 2, tg = lane & 3;
    const int lrb  = warp * 16;
    const int rb   = seg * SEG_ROWS + lrb;

    const size_t base = (size_t)(b * TOW + w) * NWIN * QKV_N + h * HD; // halves
    const __half* __restrict__ Qh = (const __half*)g_qkv + base;
    const __half* __restrict__ Kh = Qh + 192;
    const __half* __restrict__ Vh = Qh + 384;
    const uint32_t kvbase = smem_u32(KV);
    const uint32_t qsbase = smem_u32(Qs);

    // --- phase 1: cp.async K (144 rows x 16 words) + Q segment (48 x 16) ---
    for (int idx = tid; idx < NWIN * 4; idx += ATTN_THREADS) {
        const int i = idx >> 2, wc = idx & 3;
        cp16(kvbase + (uint32_t)(i * KPW + wc * 4) * 4,
             &Kh[(size_t)i * QKV_N + wc * 8]);
    }
    for (int idx = tid; idx < SEG_ROWS * 4; idx += ATTN_THREADS) {
        const int i = idx >> 2, wc = idx & 3;
        cp16(qsbase + (uint32_t)(i * QPW + wc * 4) * 4,
             &Qh[(size_t)(seg * SEG_ROWS + i) * QKV_N + wc * 8]);
    }
    CP_COMMIT();
    CP_WAIT(0);
    __syncthreads();

    // Q fragments from smem (f16 A-frag; 2 k16 blocks)
    uint32_t aq[2][4];
#pragma unroll
    for (int kb = 0; kb < 2; kb++) {
        const int k8 = kb * 8;
        aq[kb][0] = Qs[(lrb + grp) * QPW + k8 + tg];
        aq[kb][1] = Qs[(lrb + grp + 8) * QPW + k8 + tg];
        aq[kb][2] = Qs[(lrb + grp) * QPW + k8 + tg + 4];
        aq[kb][3] = Qs[(lrb + grp + 8) * QPW + k8 + tg + 4];
    }

    // --- phase 2: S = Q K^T + bias (registers, f16 mma) ---
    const float* bptr = g_biasg + (size_t)(h * TOW + w) * (NWIN * NWIN)
                        + (size_t)(seg * 3 + warp) * 2304;
    float sc[18][4];
#pragma unroll 3
    for (int nt = 0; nt < 18; nt++) {
        const int nb = nt * 8;
        float c0 = 0.f, c1 = 0.f, c2 = 0.f, c3 = 0.f;
#pragma unroll
        for (int kb = 0; kb < 2; kb++) {
            const int k8 = kb * 8;
            uint32_t b0 = KV[(nb + grp) * KPW + k8 + tg];
            uint32_t b1 = KV[(nb + grp) * KPW + k8 + tg + 4];
            mma_f16_16x8x16(c0, c1, c2, c3,
                            aq[kb][0], aq[kb][1], aq[kb][2], aq[kb][3], b0, b1);
        }
        float2 bv0 = *(const float2*)&bptr[nt * 128 + lane * 2];
        float2 bv1 = *(const float2*)&bptr[nt * 128 + 64 + lane * 2];
        sc[nt][0] = c0 + bv0.x; sc[nt][1] = c1 + bv0.y;
        sc[nt][2] = c2 + bv1.x; sc[nt][3] = c3 + bv1.y;
    }
    __syncthreads();   // K consumed; KV buffer free for vh

    // --- phase 3: stage V as token-pair half2 via byte_perm (overlaps softmax)
    // vh[i2][e] = half2(V[2i2][e], V[2i2+1][e]), pitch 40
    for (int idx = tid; idx < 72 * 8; idx += ATTN_THREADS) {
        const int i2 = idx >> 3, e0 = (idx & 7) * 4;
        uint2 u0 = *(const uint2*)&Vh[(size_t)(2 * i2) * QKV_N + e0];
        uint2 u1 = *(const uint2*)&Vh[(size_t)(2 * i2 + 1) * QKV_N + e0];
        uint4 o;
        o.x = __byte_perm(u0.x, u1.x, 0x5410);
        o.y = __byte_perm(u0.x, u1.x, 0x7632);
        o.z = __byte_perm(u0.y, u1.y, 0x5410);
        o.w = __byte_perm(u0.y, u1.y, 0x7632);
        *(uint4*)&KV[i2 * VHP + e0] = o;
    }

    float inv0, inv1;
    uint32_t ph[36];
    {
        float mx0 = -1e30f, mx1 = -1e30f;
#pragma unroll
        for (int nt = 0; nt < 18; nt++) {
            mx0 = fmaxf(mx0, fmaxf(sc[nt][0], sc[nt][1]));
            mx1 = fmaxf(mx1, fmaxf(sc[nt][2], sc[nt][3]));
        }
        mx0 = fmaxf(mx0, __shfl_xor_sync(0xffffffffu, mx0, 1));
        mx0 = fmaxf(mx0, __shfl_xor_sync(0xffffffffu, mx0, 2));
        mx1 = fmaxf(mx1, __shfl_xor_sync(0xffffffffu, mx1, 1));
        mx1 = fmaxf(mx1, __shfl_xor_sync(0xffffffffu, mx1, 2));
        float s0 = 0.f, s1 = 0.f;
#pragma unroll
        for (int nt = 0; nt < 18; nt++) {
            sc[nt][0] = ex2_approx(sc[nt][0] - mx0); s0 += sc[nt][0];
            sc[nt][1] = ex2_approx(sc[nt][1] - mx0); s0 += sc[nt][1];
            sc[nt][2] = ex2_approx(sc[nt][2] - mx1); s1 += sc[nt][2];
            sc[nt][3] = ex2_approx(sc[nt][3] - mx1); s1 += sc[nt][3];
        }
        s0 += __shfl_xor_sync(0xffffffffu, s0, 1);
        s0 += __shfl_xor_sync(0xffffffffu, s0, 2);
        s1 += __shfl_xor_sync(0xffffffffu, s1, 1);
        s1 += __shfl_xor_sync(0xffffffffu, s1, 2);
        inv0 = 1.f / s0; inv1 = 1.f / s1;
#pragma unroll
        for (int nt = 0; nt < 18; nt++) {
            ph[2 * nt]     = h2pack(sc[nt][0], sc[nt][1]);
            ph[2 * nt + 1] = h2pack(sc[nt][2], sc[nt][3]);
        }
    }
    __syncthreads();   // vh staged

    // --- phase 4: O = P V in f16 (9 k-steps, no shuffles) ---
    float c[4][4];
#pragma unroll
    for (int nt = 0; nt < 4; nt++)
#pragma unroll
        for (int r = 0; r < 4; r++) c[nt][r] = 0.f;

#pragma unroll
    for (int kk = 0; kk < 9; kk++) {
        const uint32_t a0 = ph[4 * kk + 0];
        const uint32_t a1 = ph[4 * kk + 1];
        const uint32_t a2 = ph[4 * kk + 2];
        const uint32_t a3 = ph[4 * kk + 3];
        const int r0 = (8 * kk + tg) * VHP;
        const int r1 = (8 * kk + tg + 4) * VHP;
#pragma unroll
        for (int nt = 0; nt < 4; nt++) {
            const int e = nt * 8 + grp;
            uint32_t b0 = KV[r0 + e];
            uint32_t b1 = KV[r1 + e];
            mma_f16_16x8x16(c[nt][0], c[nt][1], c[nt][2], c[nt][3],
                            a0, a1, a2, a3, b0, b1);
        }
    }

    // epilogue: normalize, store half2
    uint32_t* Oat = g_att;
    const size_t obase = (size_t)(b * TOW + w) * NWIN * DIMC + h * HD;  // halves
#pragma unroll
    for (int nt = 0; nt < 4; nt++) {
        const int col = nt * 8 + tg * 2;
        Oat[(obase + (size_t)(rb + grp) * DIMC + col) >> 1] =
            h2pack(c[nt][0] * inv0, c[nt][1] * inv0);
        Oat[(obase + (size_t)(rb + grp + 8) * DIMC + col) >> 1] =
            h2pack(c[nt][2] * inv1, c[nt][3] * inv1);
    }
}

// ---------------------------------------------------------------------------
extern "C" void kernel_launch(void* const* d_in, const int* in_sizes, int n_in,
                              void* d_out, int out_size)
{
    const float* x      = (const float*)d_in[0];
    const float* qkv_w  = (const float*)d_in[1];
    const float* qkv_b  = (const float*)d_in[2];
    const float* proj_w = (const float*)d_in[3];
    const float* proj_b = (const float*)d_in[4];
    const float* table  = (const float*)d_in[5];
    const int*   pos    = (const int*)d_in[6];
    float* out = (float*)d_out;

    uint32_t *qkv_s, *att_s, *xt_s, *wq_s, *wp_s;
    cudaGetSymbolAddress((void**)&qkv_s, g_qkv);
    cudaGetSymbolAddress((void**)&att_s, g_att);
    cudaGetSymbolAddress((void**)&xt_s,  g_xt);
    cudaGetSymbolAddress((void**)&wq_s,  g_wq);
    cudaGetSymbolAddress((void**)&wp_s,  g_wp);

    cudaFuncSetAttribute(gemm_f16_kernel, cudaFuncAttributeMaxDynamicSharedMemorySize,
                         GEMM_SMEM_B);
    cudaFuncSetAttribute(attn_mma_kernel, cudaFuncAttributeMaxDynamicSharedMemorySize,
                         ATTN_SMEM_B);

    // 0) pre-round inputs to f16; transpose bias table (xLOG2E)
    {
        int n4 = MTOT * DIMC / 4;
        cvt_f16_kernel<<<(n4 + 255) / 256, 256>>>(x, xt_s, n4);
        int w4 = QKV_N * DIMC / 4;
        cvt_f16_kernel<<<(w4 + 255) / 256, 256>>>(qkv_w, wq_s, w4);
        int p4 = DIMC * DIMC / 4;
        cvt_f16_kernel<<<(p4 + 255) / 256, 256>>>(proj_w, wp_s, p4);
        dim3 tg_(TOW, NHEADS);
        table_transpose_kernel<<<tg_, 256>>>(table);
    }
    // 1) bias pre-gather
    {
        dim3 grid(TOW, NHEADS);
        bias_gather_kernel<<<grid, 256>>>(pos);
    }
    // 2) fused QKV projection (f16; q scaled by ATT_SCALE*LOG2E; half output)
    {
        dim3 grid(QKV_N / 64, MTOT / 128);
        gemm_f16_kernel<<<grid, 256, GEMM_SMEM_B>>>(
            (const __half*)xt_s, (const __half*)wq_s, qkv_b,
            nullptr, qkv_s, QKV_N, DIMC, ATT_SCALE * LOG2E, 1);
    }
    // 3) windowed attention (all f16 tensor ops)
    {
        dim3 grid(TOW, BATCH, NHEADS * NSEG);
        attn_mma_kernel<<<grid, ATTN_THREADS, ATTN_SMEM_B>>>();
    }
    // 4) output projection (f16 inputs, fp32 output)
    {
        dim3 grid(DIMC / 64, MTOT / 128);
        gemm_f16_kernel<<<grid, 256, GEMM_SMEM_B>>>(
            (const __half*)att_s, (const __half*)wp_s, proj_b,
            out, nullptr, DIMC, 0, 1.0f, 0);
    }
}